// round 5
// baseline (speedup 1.0000x reference)
#include <cuda_runtime.h>
#include <cstdint>

#define NWARPS 4           // warps per block
#define PAIRS  8           // token pairs per warp tile
#define TOKPT  16          // tokens per warp tile
#define DIMK   32
#define NHEAD  4
#define NMAT   5           // Wv + 4*Wk
#define KT_STRIDE 36       // floats per keyT row (16B-aligned, phase-conflict-free)
#define KT_FLOATS (64 * KT_STRIDE)

struct __align__(16) Smem {
    float2 w2[NMAT][DIMK / 2][DIMK];     // [m][d2][k]
    float  bias[NMAT][DIMK];
    float  g12p[NHEAD][36];              // padded; float4 @ (o*36+4*l8) is 16B-aligned
    float  gate[NWARPS][64];             // [h*16 + t]
    float4 sums[NWARPS][64];             // (kss, qss, pdot, -) per combo c = 4t+h
    float  scratch[NWARPS][KT_FLOATS];   // union: emb stage (512 f) / keyT (2304 f)
};

__device__ __forceinline__ uint64_t pack2(float lo, float hi) {
    uint64_t r; asm("mov.b64 %0,{%1,%2};" : "=l"(r) : "f"(lo), "f"(hi)); return r;
}
__device__ __forceinline__ void unpack2(uint64_t v, float& a, float& b) {
    asm("mov.b64 {%0,%1},%2;" : "=f"(a), "=f"(b) : "l"(v));
}
__device__ __forceinline__ uint64_t ffma2(uint64_t a, uint64_t b, uint64_t c) {
    uint64_t d; asm("fma.rn.f32x2 %0,%1,%2,%3;" : "=l"(d) : "l"(a), "l"(b), "l"(c)); return d;
}
__device__ __forceinline__ uint64_t fadd2(uint64_t a, uint64_t b) {
    uint64_t d; asm("add.rn.f32x2 %0,%1,%2;" : "=l"(d) : "l"(a), "l"(b)); return d;
}
__device__ __forceinline__ uint64_t fmul2(uint64_t a, uint64_t b) {
    uint64_t d; asm("mul.rn.f32x2 %0,%1,%2;" : "=l"(d) : "l"(a), "l"(b)); return d;
}
__device__ __forceinline__ uint64_t shflx64(uint64_t v, int m) {
    uint32_t lo = (uint32_t)v, hi = (uint32_t)(v >> 32);
    lo = __shfl_xor_sync(0xffffffffu, lo, m);
    hi = __shfl_xor_sync(0xffffffffu, hi, m);
    return ((uint64_t)hi << 32) | lo;
}
__device__ __forceinline__ float rsqrt_a(float x){ float r; asm("rsqrt.approx.f32 %0,%1;" : "=f"(r) : "f"(x)); return r; }
__device__ __forceinline__ float sqrt_a (float x){ float r; asm("sqrt.approx.f32 %0,%1;"  : "=f"(r) : "f"(x)); return r; }
__device__ __forceinline__ float ex2_a  (float x){ float r; asm("ex2.approx.f32 %0,%1;"   : "=f"(r) : "f"(x)); return r; }
__device__ __forceinline__ float rcp_a  (float x){ float r; asm("rcp.approx.f32 %0,%1;"   : "=f"(r) : "f"(x)); return r; }

__global__ void __launch_bounds__(NWARPS * 32, 3)
engram_kernel(const float* __restrict__ emb,
              const float* __restrict__ hid,
              const float* __restrict__ Wv,
              const float* __restrict__ bv,
              const float* __restrict__ Wk,
              const float* __restrict__ bk,
              const float* __restrict__ g1,
              const float* __restrict__ g2,
              float* __restrict__ out,
              int ntiles)
{
    extern __shared__ char smem_raw[];
    Smem& s = *reinterpret_cast<Smem*>(smem_raw);

    const int tid  = threadIdx.x;
    const int lane = tid & 31;
    const int warp = tid >> 5;

    // ---- one-time setup ----
    for (int i = tid; i < NMAT * (DIMK / 2) * DIMK; i += blockDim.x) {
        int m   = i / ((DIMK / 2) * DIMK);
        int rem = i % ((DIMK / 2) * DIMK);
        int d2  = rem / DIMK;
        int k   = rem % DIMK;
        const float* W = (m == 0) ? Wv : (Wk + (size_t)(m - 1) * DIMK * DIMK);
        s.w2[m][d2][k] = make_float2(W[k * DIMK + 2 * d2], W[k * DIMK + 2 * d2 + 1]);
    }
    if (tid < DIMK) s.bias[0][tid] = bv[tid];
    for (int i = tid; i < NHEAD * DIMK; i += blockDim.x) {
        s.bias[1 + i / DIMK][i % DIMK] = bk[i];
        s.g12p[i / DIMK][i % DIMK] = g1[i] * g2[i];
    }
    __syncthreads();

    const float EPSF  = 1.1920929e-07f;
    const float INV32 = 0.03125f;
    const float ISQ32 = 0.17677669529663687f;   // 1/sqrt(32)
    const float LOG2E = 1.4426950408889634f;

    const int o  = lane >> 3;     // head owned by this octet
    const int l8 = lane & 7;      // 4-float k-chunk within head
    const float4 gvec = *reinterpret_cast<const float4*>(&s.g12p[o][4 * l8]);

    float*  sc   = s.scratch[warp];
    float2* embs = reinterpret_cast<float2*>(sc);
    const float4* emb4 = reinterpret_cast<const float4*>(sc);

    for (int tile = blockIdx.x * NWARPS + warp; tile < ntiles;
         tile += gridDim.x * NWARPS) {

        const int base = tile * TOKPT;

        // ---- stage emb pairs ----
        const float* embp = emb + (size_t)base * DIMK;
#pragma unroll
        for (int p = 0; p < PAIRS; ++p) {
            float e0 = embp[(2 * p) * DIMK + lane];
            float e1 = embp[(2 * p + 1) * DIMK + lane];
            embs[p * DIMK + lane] = make_float2(e0, e1);
        }
        __syncwarp();

        // ---- accumulators: acc[mat][pair] packs 2 tokens, lane = k ----
        uint64_t acc[NMAT][PAIRS];
#pragma unroll
        for (int m = 0; m < NMAT; ++m) {
            float b = s.bias[m][lane];
            uint64_t b2 = pack2(b, b);
#pragma unroll
            for (int p = 0; p < PAIRS; ++p) acc[m][p] = b2;
        }

        // ---- GEMV ----
#pragma unroll 4
        for (int d2 = 0; d2 < DIMK / 2; ++d2) {
            uint64_t wa[NMAT], wb[NMAT];
#pragma unroll
            for (int m = 0; m < NMAT; ++m) {
                float2 w = s.w2[m][d2][lane];
                wa[m] = pack2(w.x, w.x);
                wb[m] = pack2(w.y, w.y);
            }
#pragma unroll
            for (int p = 0; p < PAIRS; ++p) {
                float4 e = emb4[p * (DIMK / 2) + d2];
                uint64_t ea = pack2(e.x, e.y);
                uint64_t eb = pack2(e.z, e.w);
#pragma unroll
                for (int m = 0; m < NMAT; ++m) {
                    acc[m][p] = ffma2(ea, wa[m], acc[m][p]);
                    acc[m][p] = ffma2(eb, wb[m], acc[m][p]);
                }
            }
        }
        __syncwarp();   // emb stage dead; scratch becomes keyT

        // ---- transpose keys: row c = 4t + h, stride 36 ----
#pragma unroll
        for (int h = 0; h < NHEAD; ++h)
#pragma unroll
            for (int p = 0; p < PAIRS; ++p) {
                float lo, hi; unpack2(acc[1 + h][p], lo, hi);
                sc[(8 * p + h)     * KT_STRIDE + lane] = lo;   // t = 2p
                sc[(8 * p + 4 + h) * KT_STRIDE + lane] = hi;   // t = 2p+1
            }
        __syncwarp();

        // ---- phase A: coalesced q + octet reductions ----
        const float4* qbase = reinterpret_cast<const float4*>(hid) + (size_t)base * 32;
#pragma unroll 8
        for (int t = 0; t < TOKPT; ++t) {
            float4 q  = qbase[t * 32 + lane];                       // 512B contiguous
            float4 k4 = *reinterpret_cast<const float4*>(
                sc + (4 * t + o) * KT_STRIDE + 4 * l8);             // conflict-free

            float kss = k4.x * k4.x;
            kss = fmaf(k4.y, k4.y, kss);
            kss = fmaf(k4.z, k4.z, kss);
            kss = fmaf(k4.w, k4.w, kss);
            float qss = q.x * q.x;
            qss = fmaf(q.y, q.y, qss);
            qss = fmaf(q.z, q.z, qss);
            qss = fmaf(q.w, q.w, qss);
            float pdot = k4.x * q.x * gvec.x;
            pdot = fmaf(k4.y * q.y, gvec.y, pdot);
            pdot = fmaf(k4.z * q.z, gvec.z, pdot);
            pdot = fmaf(k4.w * q.w, gvec.w, pdot);

            uint64_t kq = pack2(kss, qss);
            kq   = fadd2(kq, shflx64(kq, 1));
            pdot += __shfl_xor_sync(0xffffffffu, pdot, 1);
            kq   = fadd2(kq, shflx64(kq, 2));
            pdot += __shfl_xor_sync(0xffffffffu, pdot, 2);
            kq   = fadd2(kq, shflx64(kq, 4));
            pdot += __shfl_xor_sync(0xffffffffu, pdot, 4);

            if (l8 == 0) {
                float ks, qs; unpack2(kq, ks, qs);
                s.sums[warp][4 * t + o] = make_float4(ks, qs, pdot, 0.f);
            }
        }
        __syncwarp();

        // ---- phase B: 64 gates at full lane efficiency ----
#pragma unroll
        for (int r = 0; r < 2; ++r) {
            int c = r * 32 + lane;                 // c = 4t + h
            float4 sv = s.sums[warp][c];
            float rk = rsqrt_a(fmaf(sv.x, INV32, EPSF));
            float rq = rsqrt_a(fmaf(sv.y, INV32, EPSF));
            float gp = sv.z * rk * rq * ISQ32;
            float a  = fmaxf(fabsf(gp), 1e-6f);
            float sr = copysignf(sqrt_a(a), gp);
            float ex = ex2_a(-sr * LOG2E);
            s.gate[warp][(c & 3) * 16 + (c >> 2)] = rcp_a(1.f + ex);
        }
        __syncwarp();

        // ---- output: out[tok][h][k] = gate * value ----
        float* outp = out + (size_t)base * (NHEAD * DIMK);
#pragma unroll
        for (int p = 0; p < PAIRS; ++p) {
#pragma unroll
            for (int h = 0; h < NHEAD; ++h) {
                uint64_t g2v = *reinterpret_cast<const uint64_t*>(
                    &s.gate[warp][h * 16 + 2 * p]);
                uint64_t ov = fmul2(g2v, acc[0][p]);
                float o0, o1; unpack2(ov, o0, o1);
                outp[(2 * p)     * (NHEAD * DIMK) + h * DIMK + lane] = o0;
                outp[(2 * p + 1) * (NHEAD * DIMK) + h * DIMK + lane] = o1;
            }
        }
        __syncwarp();
    }
}

extern "C" void kernel_launch(void* const* d_in, const int* in_sizes, int n_in,
                              void* d_out, int out_size)
{
    const float* emb = (const float*)d_in[0];
    const float* hid = (const float*)d_in[1];
    const float* Wv  = (const float*)d_in[2];
    const float* bv  = (const float*)d_in[3];
    const float* Wk  = (const float*)d_in[4];
    const float* bk  = (const float*)d_in[5];
    const float* g1  = (const float*)d_in[6];
    const float* g2  = (const float*)d_in[7];

    int ntok   = in_sizes[0] / DIMK;   // B*S
    int ntiles = ntok / TOKPT;

    size_t smem = sizeof(Smem);
    cudaFuncSetAttribute(engram_kernel,
                         cudaFuncAttributeMaxDynamicSharedMemorySize, (int)smem);

    int blocks = 2048;                 // 8192 warps -> 2 tiles per warp
    engram_kernel<<<blocks, NWARPS * 32, smem>>>(
        emb, hid, Wv, bv, Wk, bk, g1, g2, (float*)d_out, ntiles);
}

// round 6
// speedup vs baseline: 1.1633x; 1.1633x over previous
#include <cuda_runtime.h>
#include <cstdint>

#define NWARPS 4           // warps per block
#define PAIRS  8           // token pairs per warp tile
#define TOKPT  16          // tokens per warp tile
#define DIMK   32
#define NHEAD  4
#define NMAT   5           // Wv + 4*Wk
#define KT_STRIDE 33       // floats per keyT/qT row (scalar conflict-free)
#define KT_FLOATS (64 * KT_STRIDE)   // keyT: 64 rows
#define QT_FLOATS (32 * KT_STRIDE)   // qT: 32 rows (one 8-token round)

struct __align__(16) Smem {
    float2 w2[NMAT][DIMK / 2][DIMK];     // [m][d2][k]            20480 B
    float  bias[NMAT][DIMK];             //                         640 B
    float  g12p[NHEAD][KT_STRIDE];       // stride-33 rows          528 B
    float  gate[NWARPS][64];             // [h*16 + t]             1024 B
    float  scratch[NWARPS][KT_FLOATS];   // emb stage / keyT      33792 B
    float  qT[NWARPS][QT_FLOATS];        // staged q (per round)  16896 B
};                                       // total ~73.4 KB -> 3 CTAs/SM

__device__ __forceinline__ uint64_t pack2(float lo, float hi) {
    uint64_t r; asm("mov.b64 %0,{%1,%2};" : "=l"(r) : "f"(lo), "f"(hi)); return r;
}
__device__ __forceinline__ void unpack2(uint64_t v, float& a, float& b) {
    asm("mov.b64 {%0,%1},%2;" : "=f"(a), "=f"(b) : "l"(v));
}
__device__ __forceinline__ uint64_t ffma2(uint64_t a, uint64_t b, uint64_t c) {
    uint64_t d; asm("fma.rn.f32x2 %0,%1,%2,%3;" : "=l"(d) : "l"(a), "l"(b), "l"(c)); return d;
}
__device__ __forceinline__ uint64_t fmul2(uint64_t a, uint64_t b) {
    uint64_t d; asm("mul.rn.f32x2 %0,%1,%2;" : "=l"(d) : "l"(a), "l"(b)); return d;
}
__device__ __forceinline__ float rsqrt_a(float x){ float r; asm("rsqrt.approx.f32 %0,%1;" : "=f"(r) : "f"(x)); return r; }
__device__ __forceinline__ float sqrt_a (float x){ float r; asm("sqrt.approx.f32 %0,%1;"  : "=f"(r) : "f"(x)); return r; }
__device__ __forceinline__ float ex2_a  (float x){ float r; asm("ex2.approx.f32 %0,%1;"   : "=f"(r) : "f"(x)); return r; }
__device__ __forceinline__ float rcp_a  (float x){ float r; asm("rcp.approx.f32 %0,%1;"   : "=f"(r) : "f"(x)); return r; }

__global__ void __launch_bounds__(NWARPS * 32, 3)
engram_kernel(const float* __restrict__ emb,
              const float* __restrict__ hid,
              const float* __restrict__ Wv,
              const float* __restrict__ bv,
              const float* __restrict__ Wk,
              const float* __restrict__ bk,
              const float* __restrict__ g1,
              const float* __restrict__ g2,
              float* __restrict__ out,
              int ntiles)
{
    extern __shared__ char smem_raw[];
    Smem& s = *reinterpret_cast<Smem*>(smem_raw);

    const int tid  = threadIdx.x;
    const int lane = tid & 31;
    const int warp = tid >> 5;

    // ---- one-time setup ----
    for (int i = tid; i < NMAT * (DIMK / 2) * DIMK; i += blockDim.x) {
        int m   = i / ((DIMK / 2) * DIMK);
        int rem = i % ((DIMK / 2) * DIMK);
        int d2  = rem / DIMK;
        int k   = rem % DIMK;
        const float* W = (m == 0) ? Wv : (Wk + (size_t)(m - 1) * DIMK * DIMK);
        s.w2[m][d2][k] = make_float2(W[k * DIMK + 2 * d2], W[k * DIMK + 2 * d2 + 1]);
    }
    if (tid < DIMK) s.bias[0][tid] = bv[tid];
    for (int i = tid; i < NHEAD * DIMK; i += blockDim.x) {
        s.bias[1 + i / DIMK][i % DIMK] = bk[i];
        s.g12p[i / DIMK][i % DIMK] = g1[i] * g2[i];
    }
    __syncthreads();

    const float EPSF  = 1.1920929e-07f;
    const float INV32 = 0.03125f;
    const float ISQ32 = 0.17677669529663687f;   // 1/sqrt(32)
    const float LOG2E = 1.4426950408889634f;

    float*  sc   = s.scratch[warp];
    float*  qt   = s.qT[warp];
    float2* embs = reinterpret_cast<float2*>(sc);
    const float4* emb4 = reinterpret_cast<const float4*>(sc);

    const int o  = lane >> 3;   // staging: head of this lane's float4
    const int l8 = lane & 7;    // staging: 4-float chunk within head

    for (int tile = blockIdx.x * NWARPS + warp; tile < ntiles;
         tile += gridDim.x * NWARPS) {

        const int base = tile * TOKPT;

        // ---- stage emb pairs ----
        const float* embp = emb + (size_t)base * DIMK;
#pragma unroll
        for (int p = 0; p < PAIRS; ++p) {
            float e0 = embp[(2 * p) * DIMK + lane];
            float e1 = embp[(2 * p + 1) * DIMK + lane];
            embs[p * DIMK + lane] = make_float2(e0, e1);
        }
        __syncwarp();

        // ---- accumulators: acc[mat][pair] packs 2 tokens, lane = k ----
        uint64_t acc[NMAT][PAIRS];
#pragma unroll
        for (int m = 0; m < NMAT; ++m) {
            float b = s.bias[m][lane];
            uint64_t b2 = pack2(b, b);
#pragma unroll
            for (int p = 0; p < PAIRS; ++p) acc[m][p] = b2;
        }

        // ---- GEMV ----
#pragma unroll 4
        for (int d2 = 0; d2 < DIMK / 2; ++d2) {
            uint64_t wa[NMAT], wb[NMAT];
#pragma unroll
            for (int m = 0; m < NMAT; ++m) {
                float2 w = s.w2[m][d2][lane];
                wa[m] = pack2(w.x, w.x);
                wb[m] = pack2(w.y, w.y);
            }
#pragma unroll
            for (int p = 0; p < PAIRS; ++p) {
                float4 e = emb4[p * (DIMK / 2) + d2];
                uint64_t ea = pack2(e.x, e.y);
                uint64_t eb = pack2(e.z, e.w);
#pragma unroll
                for (int m = 0; m < NMAT; ++m) {
                    acc[m][p] = ffma2(ea, wa[m], acc[m][p]);
                    acc[m][p] = ffma2(eb, wb[m], acc[m][p]);
                }
            }
        }
        __syncwarp();   // emb stage dead; scratch becomes keyT

        // ---- transpose keys: row c = 4t + h, stride 33, conflict-free ----
#pragma unroll
        for (int h = 0; h < NHEAD; ++h)
#pragma unroll
            for (int p = 0; p < PAIRS; ++p) {
                float lo, hi; unpack2(acc[1 + h][p], lo, hi);
                sc[(8 * p + h)     * KT_STRIDE + lane] = lo;   // t = 2p
                sc[(8 * p + 4 + h) * KT_STRIDE + lane] = hi;   // t = 2p+1
            }
        __syncwarp();

        // ---- combo: 2 rounds of (stage 8 q-tokens coalesced, then serial gates) ----
        const float4* hid4 = reinterpret_cast<const float4*>(hid) + (size_t)base * 32;
#pragma unroll
        for (int r = 0; r < 2; ++r) {
            // stage q rows c_local = 4*tl + head, stride 33 (conflict-free STS.32)
#pragma unroll
            for (int tl = 0; tl < 8; ++tl) {
                float4 Q = hid4[(r * 8 + tl) * 32 + lane];
                float* dst = qt + (4 * tl + o) * KT_STRIDE + 4 * l8;
                dst[0] = Q.x; dst[1] = Q.y; dst[2] = Q.z; dst[3] = Q.w;
            }
            __syncwarp();

            // lane owns combo c = 32r + lane:  h = lane&3, t = 8r + (lane>>2)
            const int h = lane & 3;
            const int t = r * 8 + (lane >> 2);
            const float* keyrow = sc + (32 * r + lane) * KT_STRIDE;
            const float* qrow   = qt + lane * KT_STRIDE;
            const float* grow   = s.g12p[h];

            float kss = 0.f, qss = 0.f, pdot = 0.f;
#pragma unroll
            for (int kk = 0; kk < 8; ++kk) {
#pragma unroll
                for (int j = 0; j < 4; ++j) {
                    float kv = keyrow[4 * kk + j];
                    float qv = qrow[4 * kk + j];
                    float gv = grow[4 * kk + j];     // broadcast within head octets
                    kss  = fmaf(kv, kv, kss);
                    qss  = fmaf(qv, qv, qss);
                    pdot = fmaf(kv * qv, gv, pdot);
                }
            }

            float rk = rsqrt_a(fmaf(kss, INV32, EPSF));
            float rq = rsqrt_a(fmaf(qss, INV32, EPSF));
            float gp = pdot * rk * rq * ISQ32;
            float a  = fmaxf(fabsf(gp), 1e-6f);
            float sr = copysignf(sqrt_a(a), gp);
            float ex = ex2_a(-sr * LOG2E);
            s.gate[warp][h * 16 + t] = rcp_a(1.f + ex);
            __syncwarp();   // qT reused next round / gates ready
        }

        // ---- output: out[tok][h][k] = gate * value ----
        float* outp = out + (size_t)base * (NHEAD * DIMK);
#pragma unroll
        for (int p = 0; p < PAIRS; ++p) {
#pragma unroll
            for (int h = 0; h < NHEAD; ++h) {
                uint64_t g2v = *reinterpret_cast<const uint64_t*>(
                    &s.gate[warp][h * 16 + 2 * p]);
                uint64_t ov = fmul2(g2v, acc[0][p]);
                float o0, o1; unpack2(ov, o0, o1);
                outp[(2 * p)     * (NHEAD * DIMK) + h * DIMK + lane] = o0;
                outp[(2 * p + 1) * (NHEAD * DIMK) + h * DIMK + lane] = o1;
            }
        }
        __syncwarp();
    }
}

extern "C" void kernel_launch(void* const* d_in, const int* in_sizes, int n_in,
                              void* d_out, int out_size)
{
    const float* emb = (const float*)d_in[0];
    const float* hid = (const float*)d_in[1];
    const float* Wv  = (const float*)d_in[2];
    const float* bv  = (const float*)d_in[3];
    const float* Wk  = (const float*)d_in[4];
    const float* bk  = (const float*)d_in[5];
    const float* g1  = (const float*)d_in[6];
    const float* g2  = (const float*)d_in[7];

    int ntok   = in_sizes[0] / DIMK;   // B*S
    int ntiles = ntok / TOKPT;

    size_t smem = sizeof(Smem);
    cudaFuncSetAttribute(engram_kernel,
                         cudaFuncAttributeMaxDynamicSharedMemorySize, (int)smem);

    int blocks = 2048;                 // 8192 warps -> 2 tiles per warp
    engram_kernel<<<blocks, NWARPS * 32, smem>>>(
        emb, hid, Wv, bv, Wk, bk, g1, g2, (float*)d_out, ntiles);
}